// round 2
// baseline (speedup 1.0000x reference)
#include <cuda_runtime.h>
#include <cuda_bf16.h>
#include <cstdint>

// ---------------- problem constants ----------------
// xs: [16,128,24,24,24] f32 ; fv: [128,128,3,3,3] f32 ; out: [16,128,22,22,22] f32
#define BATCH 16
#define CHAN  128
#define NF    128
#define SP_IN   13824          // 24^3
#define SP_OUT  10648          // 22^3
#define NPOS    170368         // 16*10648
#define NTILES  1331           // NPOS/128
#define NCHUNK  54             // 27 offsets * 2 half-C chunks (K=64 each)

// ---------------- device scratch ----------------
__device__ __nv_bfloat16 g_Xb[BATCH * SP_IN * CHAN];   // channels-last bf16
__device__ float         g_S [BATCH * SP_IN];          // per-voxel sum_c x^2
__device__ __nv_bfloat16 g_Wb[27 * NF * CHAN];         // [off][f][c]
__device__ float         g_p2[NF];

// smem: [0,512) x2s ; [512,1024) p2s ; [1024,1536) nbs ; [1536,2048) nss ;
//       [2048, 2048+3*32768) pipeline stages (A 16KB + B 16KB each)
#define OFF_STAGE 2048
#define SMEM_BYTES (OFF_STAGE + 3 * 32768)

// ---------------- PTX helpers (base-target only; NO tcgen05) ----------------
__device__ __forceinline__ uint32_t smem_u32(const void* p) {
    uint32_t a;
    asm("{ .reg .u64 t; cvta.to.shared.u64 t, %1; cvt.u32.u64 %0, t; }" : "=r"(a) : "l"(p));
    return a;
}
__device__ __forceinline__ void cp16(uint32_t dst, const void* src) {
    asm volatile("cp.async.cg.shared.global [%0], [%1], 16;" :: "r"(dst), "l"(src) : "memory");
}
#define CP_COMMIT() asm volatile("cp.async.commit_group;" ::: "memory")
#define CP_WAIT2()  asm volatile("cp.async.wait_group 2;"  ::: "memory")

__device__ __forceinline__ void ldsm4(uint32_t (&r)[4], uint32_t addr) {
    asm volatile("ldmatrix.sync.aligned.m8n8.x4.shared.b16 {%0,%1,%2,%3}, [%4];"
                 : "=r"(r[0]), "=r"(r[1]), "=r"(r[2]), "=r"(r[3]) : "r"(addr));
}
__device__ __forceinline__ void mma16816(float* c, const uint32_t* a, const uint32_t* b) {
    asm volatile("mma.sync.aligned.m16n8k16.row.col.f32.bf16.bf16.f32 "
                 "{%0,%1,%2,%3}, {%4,%5,%6,%7}, {%8,%9}, {%0,%1,%2,%3};"
                 : "+f"(c[0]), "+f"(c[1]), "+f"(c[2]), "+f"(c[3])
                 : "r"(a[0]), "r"(a[1]), "r"(a[2]), "r"(a[3]), "r"(b[0]), "r"(b[1]));
}

// ---------------- pre-pass 1: X -> channels-last bf16 + sum of squares ----------------
__global__ void __launch_bounds__(256) xprep_kernel(const float* __restrict__ xs) {
    __shared__ float tile[CHAN * 25];
    const int blk = blockIdx.x;                 // (b*24 + d)*24 + h
    const int tid = threadIdx.x;
    const int b   = blk / (24 * 24);
    const long inbase = (long)b * CHAN * SP_IN + (long)(blk - b * 24 * 24) * 24;
    for (int i = tid; i < CHAN * 24; i += 256) {
        int c = i / 24, w = i - c * 24;
        tile[c * 25 + w] = xs[inbase + (long)c * SP_IN + w];
    }
    __syncthreads();
    const int spb = blk * 24;
    for (int i = tid; i < CHAN * 24; i += 256) {
        int w = i >> 7, c = i & 127;
        g_Xb[(spb + w) * CHAN + c] = __float2bfloat16(tile[c * 25 + w]);
    }
    if (tid < 24) {
        float s = 0.f;
        #pragma unroll 8
        for (int c = 0; c < CHAN; c++) { float v = tile[c * 25 + tid]; s += v * v; }
        g_S[spb + tid] = s;
    }
}

// ---------------- pre-pass 2: weights -> [off][f][c] bf16 + ||p||^2 ----------------
__global__ void __launch_bounds__(256) wprep_kernel(const float* __restrict__ fv) {
    const int off = blockIdx.x;   // 0..26
    const int tid = threadIdx.x;
    for (int i = tid; i < NF * CHAN; i += 256) {
        int f = i >> 7, c = i & 127;
        g_Wb[off * NF * CHAN + i] = __float2bfloat16(fv[f * 3456 + c * 27 + off]);
    }
}
__global__ void __launch_bounds__(128) p2_kernel(const float* __restrict__ fv) {
    const int f = threadIdx.x;
    float s = 0.f;
    #pragma unroll 8
    for (int i = 0; i < 3456; i++) { float v = fv[f * 3456 + i]; s += v * v; }
    g_p2[f] = s;
}

// ---------------- main kernel: HMMA implicit-GEMM L2 conv ----------------
__global__ void __launch_bounds__(128, 2) l2conv_main_kernel(float* __restrict__ out) {
    extern __shared__ char smem[];
    const uint32_t sb = smem_u32(smem);
    const int tid  = threadIdx.x;
    const int wid  = tid >> 5;
    const int lane = tid & 31;
    const int tile_base = blockIdx.x * 128;

    float* x2s = (float*)(smem);
    float* p2s = (float*)(smem + 512);
    int*   nbs = (int*)(smem + 1024);
    int*   nss = (int*)(smem + 1536);
    const uint32_t stg = sb + OFF_STAGE;

    // per-position metadata (128 entries, 128 threads)
    {
        p2s[tid] = g_p2[tid];
        int n = tile_base + tid;
        int b = n / SP_OUT;  int rem = n - b * SP_OUT;
        int z = rem / 484;   int r2  = rem - z * 484;
        int y = r2 / 22;     int x   = r2 - y * 22;
        nbs[tid] = b;  nss[tid] = rem;
        int spb = ((b * 24 + z) * 24 + y) * 24 + x;
        float s = 0.f;
        #pragma unroll
        for (int kd = 0; kd < 3; kd++)
            #pragma unroll
            for (int kh = 0; kh < 3; kh++)
                #pragma unroll
                for (int kw = 0; kw < 3; kw++)
                    s += g_S[spb + kd * 576 + kh * 24 + kw];
        x2s[tid] = s;
    }

    // per-thread im2col row bases for the B gather (8 rows each)
    const int seg = tid & 7;
    int rbase[8];
    #pragma unroll
    for (int i = 0; i < 8; i++) {
        int r = (tid >> 3) + 16 * i;
        int n = tile_base + r;
        int b = n / SP_OUT;  int rem = n - b * SP_OUT;
        int z = rem / 484;   int r2  = rem - z * 484;
        int y = r2 / 22;     int x   = r2 - y * 22;
        rbase[i] = (((b * 24 + z) * 24 + y) * 24 + x) * CHAN;
    }
    __syncthreads();

    auto issue = [&](int chunk) {
        const int st    = chunk % 3;
        const int off   = chunk >> 1;
        const int chalf = chunk & 1;
        const int kd = off / 9, kr = off - kd * 9;
        const int kh = kr / 3,  kw = kr - kh * 3;
        const int offterm = (kd * 576 + kh * 24 + kw) * CHAN + chalf * 64 + seg * 8;
        const __nv_bfloat16* wsrc = g_Wb + off * (NF * CHAN) + chalf * 64 + seg * 8;
        const uint32_t sA = stg + st * 32768;
        const uint32_t sB = sA + 16384;
        #pragma unroll
        for (int i = 0; i < 8; i++) {
            const int r = (tid >> 3) + 16 * i;
            uint32_t so = (uint32_t)(r * 128 + seg * 16);
            so ^= (so >> 3) & 0x70;
            cp16(sA + so, wsrc + r * CHAN);
            cp16(sB + so, g_Xb + rbase[i] + offterm);
        }
    };

    // prologue: 3 stages in flight
    issue(0); CP_COMMIT();
    issue(1); CP_COMMIT();
    issue(2); CP_COMMIT();

    // warp tile: 64x64, warp grid 2(m) x 2(n)
    const int wm = wid >> 1, wn = wid & 1;
    const int arow = wm * 64 + (lane & 15);
    const int asg  = lane >> 4;                            // 0/1
    const int brow = wn * 64 + ((lane >> 4) & 1) * 8 + (lane & 7);
    const int bsg  = (lane >> 3) & 1;

    float acc[4][8][4];
    #pragma unroll
    for (int mt = 0; mt < 4; mt++)
        #pragma unroll
        for (int nt = 0; nt < 8; nt++)
            #pragma unroll
            for (int q = 0; q < 4; q++) acc[mt][nt][q] = 0.f;

    for (int chunk = 0; chunk < NCHUNK; chunk++) {
        CP_WAIT2();
        __syncthreads();
        const uint32_t aB = stg + (chunk % 3) * 32768;
        const uint32_t bB = aB + 16384;
        #pragma unroll
        for (int kk = 0; kk < 4; kk++) {
            uint32_t a[4][4], b[4][4];
            #pragma unroll
            for (int mt = 0; mt < 4; mt++) {
                const int R = arow + mt * 16;
                ldsm4(a[mt], aB + (uint32_t)(R * 128 + (((kk * 2 + asg) ^ (R & 7)) * 16)));
            }
            #pragma unroll
            for (int np = 0; np < 4; np++) {
                const int R = brow + np * 16;
                ldsm4(b[np], bB + (uint32_t)(R * 128 + (((kk * 2 + bsg) ^ (R & 7)) * 16)));
            }
            #pragma unroll
            for (int mt = 0; mt < 4; mt++)
                #pragma unroll
                for (int np = 0; np < 4; np++) {
                    mma16816(acc[mt][2 * np],     a[mt], &b[np][0]);
                    mma16816(acc[mt][2 * np + 1], a[mt], &b[np][2]);
                }
        }
        __syncthreads();                  // everyone done reading this stage
        if (chunk + 3 < NCHUNK) issue(chunk + 3);
        CP_COMMIT();                      // commit every iter (maybe-empty group)
    }

    // ---- epilogue: acc -> smem transpose -> fused L2 + coalesced store ----
    __syncthreads();
    float* stage = (float*)(smem + OFF_STAGE);   // [128 f][129] f32
    #pragma unroll
    for (int mt = 0; mt < 4; mt++)
        #pragma unroll
        for (int nt = 0; nt < 8; nt++) {
            const int m = wm * 64 + mt * 16 + (lane >> 2);
            const int n = wn * 64 + nt * 8 + (lane & 3) * 2;
            stage[m * 129 + n]           = acc[mt][nt][0];
            stage[m * 129 + n + 1]       = acc[mt][nt][1];
            stage[(m + 8) * 129 + n]     = acc[mt][nt][2];
            stage[(m + 8) * 129 + n + 1] = acc[mt][nt][3];
        }
    __syncthreads();
    const float x2 = x2s[tid];
    const long  ob = (long)nbs[tid] * (NF * SP_OUT) + nss[tid];
    #pragma unroll 4
    for (int f = 0; f < NF; f++) {
        const float conv = stage[f * 129 + tid];
        out[ob + (long)f * SP_OUT] = sqrtf(fabsf(x2 + p2s[f] - 2.0f * conv) + 1e-14f);
    }
}

// ---------------- launch ----------------
extern "C" void kernel_launch(void* const* d_in, const int* in_sizes, int n_in,
                              void* d_out, int out_size) {
    const float* xs = (const float*)d_in[0];
    const float* fv = (const float*)d_in[1];
    if (n_in >= 2 && in_sizes[0] == 128 * 128 * 27) {  // robust to input ordering
        xs = (const float*)d_in[1];
        fv = (const float*)d_in[0];
    }
    cudaFuncSetAttribute(l2conv_main_kernel,
                         cudaFuncAttributeMaxDynamicSharedMemorySize, SMEM_BYTES);
    xprep_kernel<<<BATCH * 24 * 24, 256>>>(xs);
    wprep_kernel<<<27, 256>>>(fv);
    p2_kernel<<<1, 128>>>(fv);
    l2conv_main_kernel<<<NTILES, 128, SMEM_BYTES>>>((float*)d_out);
}

// round 3
// speedup vs baseline: 1.5183x; 1.5183x over previous
#include <cuda_runtime.h>
#include <cuda_bf16.h>
#include <cstdint>

// ---------------- problem constants ----------------
// xs: [16,128,24,24,24] f32 ; fv: [128,128,3,3,3] f32 ; out: [16,128,22,22,22] f32
#define BATCH 16
#define CHAN  128
#define NF    128
#define SP_IN   13824          // 24^3
#define SP_OUT  10648          // 22^3
#define NPOS    170368         // 16*10648
#define NTILES  1331           // NPOS/128
#define NCHUNK  54             // 27 offsets * 2 half-C chunks (K=64 each)

// ---------------- device scratch ----------------
__device__ __nv_bfloat16 g_Xb[BATCH * SP_IN * CHAN];   // channels-last bf16
__device__ float         g_S [BATCH * SP_IN];          // per-voxel sum_c x^2
__device__ __nv_bfloat16 g_Wb[27 * NF * CHAN];         // [off][f][c]
__device__ float         g_p2[NF];

// smem: [0,512) x2s ; [512,1024) p2s ; [1024,1536) nbs ; [1536,2048) nss ;
//       [2048, +3*32768) pipeline stages (A 16KB + B 16KB each)
#define OFF_STAGE 2048
#define SMEM_BYTES (OFF_STAGE + 3 * 32768)

// ---------------- PTX helpers ----------------
__device__ __forceinline__ uint32_t smem_u32(const void* p) {
    uint32_t a;
    asm("{ .reg .u64 t; cvta.to.shared.u64 t, %1; cvt.u32.u64 %0, t; }" : "=r"(a) : "l"(p));
    return a;
}
__device__ __forceinline__ void cp16(uint32_t dst, const void* src) {
    asm volatile("cp.async.cg.shared.global [%0], [%1], 16;" :: "r"(dst), "l"(src) : "memory");
}
#define CP_COMMIT() asm volatile("cp.async.commit_group;" ::: "memory")
#define CP_WAIT1()  asm volatile("cp.async.wait_group 1;"  ::: "memory")

__device__ __forceinline__ void ldsm4(uint32_t (&r)[4], uint32_t addr) {
    asm volatile("ldmatrix.sync.aligned.m8n8.x4.shared.b16 {%0,%1,%2,%3}, [%4];"
                 : "=r"(r[0]), "=r"(r[1]), "=r"(r[2]), "=r"(r[3]) : "r"(addr));
}
__device__ __forceinline__ void mma16816(float* c, const uint32_t* a, const uint32_t* b) {
    asm volatile("mma.sync.aligned.m16n8k16.row.col.f32.bf16.bf16.f32 "
                 "{%0,%1,%2,%3}, {%4,%5,%6,%7}, {%8,%9}, {%0,%1,%2,%3};"
                 : "+f"(c[0]), "+f"(c[1]), "+f"(c[2]), "+f"(c[3])
                 : "r"(a[0]), "r"(a[1]), "r"(a[2]), "r"(a[3]), "r"(b[0]), "r"(b[1]));
}

// ---------------- pre-pass 1: X -> channels-last bf16 + sum of squares ----------------
__global__ void __launch_bounds__(256) xprep_kernel(const float* __restrict__ xs) {
    __shared__ float tile[CHAN * 25];
    const int blk = blockIdx.x;                 // (b*24 + d)*24 + h
    const int tid = threadIdx.x;
    const int b   = blk / (24 * 24);
    const long inbase = (long)b * CHAN * SP_IN + (long)(blk - b * 24 * 24) * 24;
    for (int i = tid; i < CHAN * 24; i += 256) {
        int c = i / 24, w = i - c * 24;
        tile[c * 25 + w] = xs[inbase + (long)c * SP_IN + w];
    }
    __syncthreads();
    const int spb = blk * 24;
    for (int i = tid; i < CHAN * 24; i += 256) {
        int w = i >> 7, c = i & 127;
        g_Xb[(spb + w) * CHAN + c] = __float2bfloat16(tile[c * 25 + w]);
    }
    if (tid < 24) {
        float s = 0.f;
        #pragma unroll 8
        for (int c = 0; c < CHAN; c++) { float v = tile[c * 25 + tid]; s += v * v; }
        g_S[spb + tid] = s;
    }
}

// ---------------- pre-pass 2 (fused): weights -> [off][f][c] bf16 AND ||p||^2 ----------------
// One block per feature f. Coalesced reads of fv[f, :]; block reduction for p2.
__global__ void __launch_bounds__(128) wp2_kernel(const float* __restrict__ fv) {
    __shared__ float red[4];
    const int f = blockIdx.x;
    const int t = threadIdx.x;
    const float* src = fv + (long)f * 3456;
    float s = 0.f;
    #pragma unroll
    for (int k = 0; k < 27; k++) {
        const int idx = k * 128 + t;          // = c*27 + off
        const float v = src[idx];             // coalesced
        s += v * v;
        const int c   = idx / 27;
        const int off = idx - c * 27;
        g_Wb[off * (NF * CHAN) + f * CHAN + c] = __float2bfloat16(v);
    }
    #pragma unroll
    for (int o = 16; o > 0; o >>= 1) s += __shfl_down_sync(0xffffffffu, s, o);
    if ((t & 31) == 0) red[t >> 5] = s;
    __syncthreads();
    if (t == 0) g_p2[f] = red[0] + red[1] + red[2] + red[3];
}

// ---------------- main kernel: HMMA implicit-GEMM L2 conv ----------------
// 256 threads = 8 warps, warp grid 2(m) x 4(n), warp tile M64 x N32.
__global__ void __launch_bounds__(256, 2) l2conv_main_kernel(float* __restrict__ out) {
    extern __shared__ char smem[];
    const uint32_t sb = smem_u32(smem);
    const int tid  = threadIdx.x;
    const int wid  = tid >> 5;
    const int lane = tid & 31;
    const int tile_base = blockIdx.x * 128;

    float* x2s = (float*)(smem);
    float* p2s = (float*)(smem + 512);
    int*   nbs = (int*)(smem + 1024);
    int*   nss = (int*)(smem + 1536);
    const uint32_t stg = sb + OFF_STAGE;

    // per-position metadata (128 entries)
    if (tid < 128) {
        p2s[tid] = g_p2[tid];
        int n = tile_base + tid;
        int b = n / SP_OUT;  int rem = n - b * SP_OUT;
        int z = rem / 484;   int r2  = rem - z * 484;
        int y = r2 / 22;     int x   = r2 - y * 22;
        nbs[tid] = b;  nss[tid] = rem;
        int spb = ((b * 24 + z) * 24 + y) * 24 + x;
        float s = 0.f;
        #pragma unroll
        for (int kd = 0; kd < 3; kd++)
            #pragma unroll
            for (int kh = 0; kh < 3; kh++)
                #pragma unroll
                for (int kw = 0; kw < 3; kw++)
                    s += g_S[spb + kd * 576 + kh * 24 + kw];
        x2s[tid] = s;
    }

    // per-thread im2col row bases for the B gather (4 rows each)
    const int seg = tid & 7;
    int rbase[4];
    #pragma unroll
    for (int i = 0; i < 4; i++) {
        int r = (tid >> 3) + 32 * i;
        int n = tile_base + r;
        int b = n / SP_OUT;  int rem = n - b * SP_OUT;
        int z = rem / 484;   int r2  = rem - z * 484;
        int y = r2 / 22;     int x   = r2 - y * 22;
        rbase[i] = (((b * 24 + z) * 24 + y) * 24 + x) * CHAN;
    }
    __syncthreads();

    auto issue = [&](int chunk) {
        const int st    = chunk % 3;
        const int off   = chunk >> 1;
        const int chalf = chunk & 1;
        const int kd = off / 9, kr = off - kd * 9;
        const int kh = kr / 3,  kw = kr - kh * 3;
        const int offterm = (kd * 576 + kh * 24 + kw) * CHAN + chalf * 64 + seg * 8;
        const __nv_bfloat16* wsrc = g_Wb + off * (NF * CHAN) + chalf * 64 + seg * 8;
        const uint32_t sA = stg + st * 32768;
        const uint32_t sB = sA + 16384;
        #pragma unroll
        for (int i = 0; i < 4; i++) {
            const int r = (tid >> 3) + 32 * i;
            uint32_t so = (uint32_t)(r * 128 + seg * 16);
            so ^= (so >> 3) & 0x70;
            cp16(sA + so, wsrc + r * CHAN);
            cp16(sB + so, g_Xb + rbase[i] + offterm);
        }
    };

    // prologue: 2 stages in flight
    issue(0); CP_COMMIT();
    issue(1); CP_COMMIT();

    const int wm = wid >> 2, wn = wid & 3;              // 2 x 4 warp grid
    const int arow = wm * 64 + (lane & 15);
    const int asg  = lane >> 4;
    const int brow = wn * 32 + ((lane >> 4) & 1) * 8 + (lane & 7);
    const int bsg  = (lane >> 3) & 1;

    float acc[4][4][4];
    #pragma unroll
    for (int mt = 0; mt < 4; mt++)
        #pragma unroll
        for (int nt = 0; nt < 4; nt++)
            #pragma unroll
            for (int q = 0; q < 4; q++) acc[mt][nt][q] = 0.f;

    for (int chunk = 0; chunk < NCHUNK; chunk++) {
        CP_WAIT1();
        __syncthreads();
        // issue into stage (chunk+2)%3 == (chunk-1)%3 : its readers all passed the
        // sync above (they finished compute(chunk-1) last iteration) -> safe.
        if (chunk + 2 < NCHUNK) issue(chunk + 2);
        CP_COMMIT();                       // always commit (keeps group count uniform)
        const uint32_t aB = stg + (chunk % 3) * 32768;
        const uint32_t bB = aB + 16384;
        #pragma unroll
        for (int kk = 0; kk < 4; kk++) {
            uint32_t a[4][4], b[2][4];
            #pragma unroll
            for (int mt = 0; mt < 4; mt++) {
                const int R = arow + mt * 16;
                ldsm4(a[mt], aB + (uint32_t)(R * 128 + (((kk * 2 + asg) ^ (R & 7)) * 16)));
            }
            #pragma unroll
            for (int np = 0; np < 2; np++) {
                const int R = brow + np * 16;
                ldsm4(b[np], bB + (uint32_t)(R * 128 + (((kk * 2 + bsg) ^ (R & 7)) * 16)));
            }
            #pragma unroll
            for (int mt = 0; mt < 4; mt++)
                #pragma unroll
                for (int np = 0; np < 2; np++) {
                    mma16816(acc[mt][2 * np],     a[mt], &b[np][0]);
                    mma16816(acc[mt][2 * np + 1], a[mt], &b[np][2]);
                }
        }
    }

    // ---- epilogue: acc -> smem transpose -> fused L2 + coalesced store ----
    __syncthreads();
    float* stage = (float*)(smem + OFF_STAGE);   // [128 f][129] f32
    #pragma unroll
    for (int mt = 0; mt < 4; mt++)
        #pragma unroll
        for (int nt = 0; nt < 4; nt++) {
            const int m = wm * 64 + mt * 16 + (lane >> 2);
            const int n = wn * 32 + nt * 8 + (lane & 3) * 2;
            stage[m * 129 + n]           = acc[mt][nt][0];
            stage[m * 129 + n + 1]       = acc[mt][nt][1];
            stage[(m + 8) * 129 + n]     = acc[mt][nt][2];
            stage[(m + 8) * 129 + n + 1] = acc[mt][nt][3];
        }
    __syncthreads();
    for (int i = tid; i < NF * 128; i += 256) {
        const int f = i >> 7, n = i & 127;
        const float conv = stage[f * 129 + n];
        out[(long)nbs[n] * (NF * SP_OUT) + (long)f * SP_OUT + nss[n]] =
            sqrtf(fabsf(x2s[n] + p2s[f] - 2.0f * conv) + 1e-14f);
    }
}

// ---------------- launch ----------------
extern "C" void kernel_launch(void* const* d_in, const int* in_sizes, int n_in,
                              void* d_out, int out_size) {
    const float* xs = (const float*)d_in[0];
    const float* fv = (const float*)d_in[1];
    if (n_in >= 2 && in_sizes[0] == 128 * 128 * 27) {  // robust to input ordering
        xs = (const float*)d_in[1];
        fv = (const float*)d_in[0];
    }
    cudaFuncSetAttribute(l2conv_main_kernel,
                         cudaFuncAttributeMaxDynamicSharedMemorySize, SMEM_BYTES);
    xprep_kernel<<<BATCH * 24 * 24, 256>>>(xs);
    wp2_kernel<<<NF, 128>>>(fv);
    l2conv_main_kernel<<<NTILES, 256, SMEM_BYTES>>>((float*)d_out);
}